// round 16
// baseline (speedup 1.0000x reference)
#include <cuda_runtime.h>
#include <cstdint>

// Problem constants (fixed by the reference)
#define NB 4
#define NN 10000
#define NE 160000
#define HH 128
#define FF 32
#define MM 256
#define BN (NB * NN)
#define EBLK 64
#define BLOCKS_PER_BATCH (NE / EBLK)  // 2500

// Expected element counts (for input identification)
#define SZ_HIDDEN (NB * NN * HH)        // 5,120,000
#define SZ_EF     (NB * NE * FF)        // 20,480,000
#define SZ_IDX    (NB * NE)             // 640,000
#define SZ_W      ((FF + 2 * HH) * MM)  // 73,728
#define SZ_B      (MM)                  // 256

// Scratch
__device__ float g_Ps[(size_t)BN * MM];
__device__ float g_Pt[(size_t)BN * MM];
__device__ int g_src[SZ_IDX];
__device__ int g_tgt[SZ_IDX];
__device__ int g_is64[2];

// ---- packed f32x2 helpers (Blackwell sm_100+: 2x fp32 FMA rate) ----
__device__ __forceinline__ unsigned long long pack2(float x) {
    unsigned long long r;
    asm("mov.b64 %0, {%1, %1};" : "=l"(r) : "f"(x));
    return r;
}
__device__ __forceinline__ void unpack2(unsigned long long p, float& lo, float& hi) {
    asm("mov.b64 {%0, %1}, %2;" : "=f"(lo), "=f"(hi) : "l"(p));
}
#define FFMA2(d, a, b, c) \
    asm("fma.rn.f32x2 %0, %1, %2, %3;" : "=l"(d) : "l"(a), "l"(b), "l"(c))

// ---------------------------------------------------------------------------
// Index dtype detection (reads only first 512 B — in-bounds for i32 or i64).
// ---------------------------------------------------------------------------
__global__ void detect_idx_kernel(const int* __restrict__ raw_a,
                                  const int* __restrict__ raw_b) {
    if (threadIdx.x == 0 && blockIdx.x == 0) {
        int oa = 0, ob = 0;
#pragma unroll
        for (int j = 1; j < 128; j += 2) { oa |= raw_a[j]; ob |= raw_b[j]; }
        g_is64[0] = (oa == 0) ? 1 : 0;
        g_is64[1] = (ob == 0) ? 1 : 0;
    }
}

// ---------------------------------------------------------------------------
// prep: zero the poisoned output AND normalize both index arrays (1 launch).
// grid sized by n4 (2.56M float4) >= 2*SZ_IDX (1.28M) index slots.
// ---------------------------------------------------------------------------
__global__ void prep_kernel(const void* __restrict__ raw_src,
                            const void* __restrict__ raw_tgt,
                            float4* __restrict__ out, int n4) {
    int i = blockIdx.x * blockDim.x + threadIdx.x;
    if (i < n4) out[i] = make_float4(0.f, 0.f, 0.f, 0.f);
    if (i < 2 * SZ_IDX) {
        int which = (i >= SZ_IDX) ? 1 : 0;
        int j = i - which * SZ_IDX;
        const void* raw = which ? raw_tgt : raw_src;
        int v;
        if (g_is64[which]) v = (int)((const long long*)raw)[j];
        else               v = ((const int*)raw)[j];
        v = (v < 0) ? 0 : (v >= NN ? NN - 1 : v);
        if (which == 0) g_src[j] = v; else g_tgt[j] = v;
    }
}

// ---------------------------------------------------------------------------
// Fused node projection GEMM (R15 winner, unchanged): Ps = X@Ws, Pt = X@Wt + b.
// Tile 64x64, 128 threads, 8x4 microtile x2 mats, packed f32x2 FMA.
// ---------------------------------------------------------------------------
__global__ __launch_bounds__(128) void node_proj_kernel(
    const float* __restrict__ X,
    const float* __restrict__ Ws,
    const float* __restrict__ Wt,
    const float* __restrict__ bias)
{
    __shared__ float As[16][64];
    __shared__ float Bs[16][64];
    __shared__ float Cs[16][64];

    const int rblk = blockIdx.x * 64;
    const int cblk = blockIdx.y * 64;
    const int t  = threadIdx.x;
    const int tx = t & 15;
    const int ty = t >> 4;

    unsigned long long accB2[8][2], accC2[8][2];
#pragma unroll
    for (int r = 0; r < 8; r++) {
        accB2[r][0] = 0ull; accB2[r][1] = 0ull;
        accC2[r][0] = 0ull; accC2[r][1] = 0ull;
    }

#pragma unroll 1
    for (int k0 = 0; k0 < HH; k0 += 16) {
        float4 av0, av1, bv0, bv1, cv0, cv1;
        {
            int i0 = t, i1 = t + 128;
            int r0 = i0 >> 2, kq0 = (i0 & 3) * 4;
            int r1 = i1 >> 2, kq1 = (i1 & 3) * 4;
            av0 = *(const float4*)&X[(size_t)(rblk + r0) * HH + k0 + kq0];
            av1 = *(const float4*)&X[(size_t)(rblk + r1) * HH + k0 + kq1];
            int kr0 = i0 >> 4, cq0 = (i0 & 15) * 4;
            int kr1 = i1 >> 4, cq1 = (i1 & 15) * 4;
            bv0 = *(const float4*)&Ws[(size_t)(k0 + kr0) * MM + cblk + cq0];
            bv1 = *(const float4*)&Ws[(size_t)(k0 + kr1) * MM + cblk + cq1];
            cv0 = *(const float4*)&Wt[(size_t)(k0 + kr0) * MM + cblk + cq0];
            cv1 = *(const float4*)&Wt[(size_t)(k0 + kr1) * MM + cblk + cq1];
            __syncthreads();
            As[kq0 + 0][r0] = av0.x; As[kq0 + 1][r0] = av0.y;
            As[kq0 + 2][r0] = av0.z; As[kq0 + 3][r0] = av0.w;
            As[kq1 + 0][r1] = av1.x; As[kq1 + 1][r1] = av1.y;
            As[kq1 + 2][r1] = av1.z; As[kq1 + 3][r1] = av1.w;
            *(float4*)&Bs[kr0][cq0] = bv0;
            *(float4*)&Bs[kr1][cq1] = bv1;
            *(float4*)&Cs[kr0][cq0] = cv0;
            *(float4*)&Cs[kr1][cq1] = cv1;
            __syncthreads();
        }

#pragma unroll
        for (int k = 0; k < 16; k++) {
            float4 a0 = *(const float4*)&As[k][ty * 8];
            float4 a1 = *(const float4*)&As[k][ty * 8 + 4];
            ulonglong2 b2 = *(const ulonglong2*)&Bs[k][tx * 4];
            ulonglong2 c2 = *(const ulonglong2*)&Cs[k][tx * 4];
            float ar[8] = {a0.x, a0.y, a0.z, a0.w, a1.x, a1.y, a1.z, a1.w};
#pragma unroll
            for (int r = 0; r < 8; r++) {
                unsigned long long ap = pack2(ar[r]);
                FFMA2(accB2[r][0], ap, b2.x, accB2[r][0]);
                FFMA2(accB2[r][1], ap, b2.y, accB2[r][1]);
                FFMA2(accC2[r][0], ap, c2.x, accC2[r][0]);
                FFMA2(accC2[r][1], ap, c2.y, accC2[r][1]);
            }
        }
    }

    float4 bvv = *(const float4*)&bias[cblk + tx * 4];

#pragma unroll
    for (int r = 0; r < 8; r++) {
        int row = rblk + ty * 8 + r;
        float4 o1, o2;
        unpack2(accB2[r][0], o1.x, o1.y);
        unpack2(accB2[r][1], o1.z, o1.w);
        unpack2(accC2[r][0], o2.x, o2.y);
        unpack2(accC2[r][1], o2.z, o2.w);
        o2.x += bvv.x; o2.y += bvv.y; o2.z += bvv.z; o2.w += bvv.w;
        *(float4*)&g_Ps[(size_t)row * MM + cblk + tx * 4] = o1;
        *(float4*)&g_Pt[(size_t)row * MM + cblk + tx * 4] = o2;
    }
}

// ---------------------------------------------------------------------------
// Edge kernel v3: 64 edges per block, 512 threads = 16 warps.
// warp = (octet, col-half): oct = warp&7 owns 8 edges; half = warp>>3 picks
// cols [half*128, half*128+128). Lane owns 4 cols. Per-thread tile is
// 8 edges x 4 cols -> ~60 regs -> 2 CTAs/SM at 512 threads = 32 warps/SM
// (2x the latency coverage of the 8x8 variant). f32x2 GEMM; phase-split
// epilogue (batched gathers -> relu -> batched red.v4).
// ---------------------------------------------------------------------------
__global__ __launch_bounds__(512, 2) void edge_kernel(
    const float* __restrict__ ef,   // [NB*NE, 32]
    const float* __restrict__ W,    // first 32 rows of W_msg, row stride 256
    float* __restrict__ out)        // [BN, 256]
{
    __shared__ float Wf[FF][MM];            // 32 KB
    __shared__ float efs_t[FF][EBLK + 8];   // [k][edge]
    __shared__ int   src_s[EBLK];
    __shared__ int   tgt_s[EBLK];

    const int t   = threadIdx.x;
    const int blk = blockIdx.x;
    const int b   = blk / BLOCKS_PER_BATCH;
    const int e0  = (blk % BLOCKS_PER_BATCH) * EBLK;
    const int ebase = b * NE + e0;

    // Stage Wf (2048 float4, 4 per thread)
    {
        float4* wsh = (float4*)&Wf[0][0];
        const float4* wg = (const float4*)W;
#pragma unroll
        for (int i = 0; i < 4; i++) wsh[t + 512 * i] = wg[t + 512 * i];
    }
    // Stage edge features transposed (512 float4, 1 per thread)
    {
        int r = t >> 3;
        int c = (t & 7) * 4;
        float4 v = *(const float4*)&ef[(size_t)(ebase + r) * FF + c];
        efs_t[c + 0][r] = v.x; efs_t[c + 1][r] = v.y;
        efs_t[c + 2][r] = v.z; efs_t[c + 3][r] = v.w;
    }
    if (t < EBLK) {
        src_s[t] = g_src[ebase + t];
        tgt_s[t] = g_tgt[ebase + t];
    }
    __syncthreads();

    const int warp = t >> 5;
    const int oct  = warp & 7;        // edge octet
    const int half = warp >> 3;       // column half
    const int lane = t & 31;
    const int c0 = half * 128 + lane * 4;
    const int nodebase = b * NN;

    unsigned long long acc[8][2];
#pragma unroll
    for (int j = 0; j < 8; j++) { acc[j][0] = 0ull; acc[j][1] = 0ull; }

#pragma unroll 8
    for (int k = 0; k < FF; k++) {
        float4 aA = *(const float4*)&efs_t[k][oct * 8];
        float4 aB = *(const float4*)&efs_t[k][oct * 8 + 4];
        ulonglong2 w2 = *(const ulonglong2*)&Wf[k][c0];
        float a[8] = {aA.x, aA.y, aA.z, aA.w, aB.x, aB.y, aB.z, aB.w};
#pragma unroll
        for (int j = 0; j < 8; j++) {
            unsigned long long ap = pack2(a[j]);
            FFMA2(acc[j][0], ap, w2.x, acc[j][0]);
            FFMA2(acc[j][1], ap, w2.y, acc[j][1]);
        }
    }

    // Unpack accumulators
    float4 m[8];
#pragma unroll
    for (int j = 0; j < 8; j++) {
        unpack2(acc[j][0], m[j].x, m[j].y);
        unpack2(acc[j][1], m[j].z, m[j].w);
    }

    // ---- Epilogue phase A: batched gathers + relu ----
#pragma unroll
    for (int j = 0; j < 8; j++) {
        const int e = oct * 8 + j;
        const int s = nodebase + src_s[e];
        const int d = nodebase + tgt_s[e];
        float4 ps = *(const float4*)&g_Ps[(size_t)s * MM + c0];
        float4 pt = *(const float4*)&g_Pt[(size_t)d * MM + c0];
        m[j].x = fmaxf(m[j].x + ps.x + pt.x, 0.f);
        m[j].y = fmaxf(m[j].y + ps.y + pt.y, 0.f);
        m[j].z = fmaxf(m[j].z + ps.z + pt.z, 0.f);
        m[j].w = fmaxf(m[j].w + ps.w + pt.w, 0.f);
    }

    // ---- Epilogue phase B: back-to-back vector reductions ----
#pragma unroll
    for (int j = 0; j < 8; j++) {
        const int e = oct * 8 + j;
        const int d = nodebase + tgt_s[e];
        float* op = &out[(size_t)d * MM + c0];
        asm volatile("red.global.add.v4.f32 [%0], {%1, %2, %3, %4};"
                     :: "l"(op), "f"(m[j].x), "f"(m[j].y), "f"(m[j].z), "f"(m[j].w)
                     : "memory");
    }
}

// ---------------------------------------------------------------------------
// kernel_launch — inputs identified BY ELEMENT COUNT; index dtype detected
// on device. Output f32 [4,10000,256].
// ---------------------------------------------------------------------------
extern "C" void kernel_launch(void* const* d_in, const int* in_sizes, int n_in,
                              void* d_out, int out_size) {
    const float* hidden = nullptr;
    const float* ef     = nullptr;
    const void*  srcs   = nullptr;
    const void*  tgts   = nullptr;
    const float* W      = nullptr;
    const float* bmsg   = nullptr;

    for (int i = 0; i < n_in; i++) {
        switch (in_sizes[i]) {
            case SZ_HIDDEN: hidden = (const float*)d_in[i]; break;
            case SZ_EF:     ef     = (const float*)d_in[i]; break;
            case SZ_W:      W      = (const float*)d_in[i]; break;
            case SZ_B:      bmsg   = (const float*)d_in[i]; break;
            case SZ_IDX:
                if (!srcs) srcs = d_in[i];
                else       tgts = d_in[i];
                break;
            default: break;
        }
    }
    float* out = (float*)d_out;

    // 0) detect index dtype; then prep = zero output + normalize indices
    detect_idx_kernel<<<1, 32>>>((const int*)srcs, (const int*)tgts);
    int n4 = out_size / 4;
    prep_kernel<<<(n4 + 255) / 256, 256>>>(srcs, tgts, (float4*)out, n4);

    // 1) fused node projections: Ps = h @ W[32:160], Pt = h @ W[160:288] + b
    dim3 gA(BN / 64, MM / 64);
    node_proj_kernel<<<gA, 128>>>(hidden,
                                  W + (size_t)FF * MM,
                                  W + (size_t)(FF + HH) * MM,
                                  bmsg);

    // 2) per-edge message + scatter-add (8e x 4c tile, 512 thr, 2 CTA/SM)
    edge_kernel<<<NB * BLOCKS_PER_BATCH, 512>>>(ef, W, out);
}